// round 7
// baseline (speedup 1.0000x reference)
#include <cuda_runtime.h>
#include <math.h>

// Problem constants (B=4, T=2048, D=1024, E=8, K=2)
#define BT           8192
#define DD           1024
#define EE           8
#define TPB          256
#define ROWS_PER_CTA 16
#define NCTA         (BT / ROWS_PER_CTA)   // 512
#define CROWS        4                     // rows per combine CTA
#define NCCTA        (BT / CROWS)          // 2048

__device__ float        g_aux_part[NCTA];
__device__ unsigned int g_ctr;             // zero-init; self-resets each launch
__device__ int2         g_idx[BT];         // selected (i0,i1) per row

// ============================ Kernel A: gating ============================
__global__ __launch_bounds__(TPB, 4) void rlgate_gate_kernel(
    const float* __restrict__ x,          // [BT, D]
    const float* __restrict__ rewards,    // [BT]
    const float* __restrict__ W,          // [D, E]
    const float* __restrict__ bias,       // [E]
    const float* __restrict__ baseline,   // scalar
    const float* __restrict__ noise,      // [BT, E]
    float* __restrict__ out,              // aux slot at out[out_size-1]
    int out_size)
{
    __shared__ float Wt[EE][DD];          // transposed gate weights, 32KB
    __shared__ float s_aux[ROWS_PER_CTA];

    const int tid  = threadIdx.x;
    const int lane = tid & 31;
    const int warp = tid >> 5;

    const int r0 = blockIdx.x * ROWS_PER_CTA + warp * 2;
    const int r1 = r0 + 1;

    const float4* x0 = (const float4*)(x + (size_t)r0 * DD);
    const float4* x1 = (const float4*)(x + (size_t)r1 * DD);

    // Prefetch first 2 x-iterations BEFORE the smem barrier (overlaps W fill).
    float4 xa0 = __ldg(x0 + lane);
    float4 xb0 = __ldg(x1 + lane);
    float4 xa1 = __ldg(x0 + lane + 32);
    float4 xb1 = __ldg(x1 + lane + 32);

    // ---- Load W [D,E] -> smem transposed Wt[E][D] (vectorized) ----
    {
        const float4* W4 = (const float4*)W;
#pragma unroll
        for (int k = 0; k < (DD * EE / 4) / TPB; k++) {
            int i = tid + k * TPB;
            float4 v = __ldg(W4 + i);
            int d  = i >> 1;
            int e0 = (i & 1) * 4;
            Wt[e0 + 0][d] = v.x;
            Wt[e0 + 1][d] = v.y;
            Wt[e0 + 2][d] = v.z;
            Wt[e0 + 3][d] = v.w;
        }
    }
    __syncthreads();

    // ---- Phase 1: logits for both rows (depth-2 pipelined) ----
    float acc0[EE], acc1[EE];
#pragma unroll
    for (int e = 0; e < EE; e++) { acc0[e] = 0.0f; acc1[e] = 0.0f; }

    const float4* Wt4 = (const float4*)Wt;   // Wt4[e*256 + j]

#pragma unroll
    for (int i = 0; i < 8; i++) {
        float4 a4 = (i & 1) ? xa1 : xa0;
        float4 b4 = (i & 1) ? xb1 : xb0;
        if (i < 6) {                          // prefetch i+2
            int jn = lane + 32 * (i + 2);
            if (i & 1) { xa1 = __ldg(x0 + jn); xb1 = __ldg(x1 + jn); }
            else       { xa0 = __ldg(x0 + jn); xb0 = __ldg(x1 + jn); }
        }
        int j = lane + 32 * i;
#pragma unroll
        for (int e = 0; e < EE; e++) {
            float4 w = Wt4[e * (DD / 4) + j];
            acc0[e] = fmaf(a4.x, w.x, fmaf(a4.y, w.y, fmaf(a4.z, w.z, fmaf(a4.w, w.w, acc0[e]))));
            acc1[e] = fmaf(b4.x, w.x, fmaf(b4.y, w.y, fmaf(b4.z, w.z, fmaf(b4.w, w.w, acc1[e]))));
        }
    }

    // Warp xor all-reduce: every lane ends with the complete sums.
#pragma unroll
    for (int e = 0; e < EE; e++) {
#pragma unroll
        for (int off = 16; off > 0; off >>= 1) {
            acc0[e] += __shfl_xor_sync(0xffffffffu, acc0[e], off);
            acc1[e] += __shfl_xor_sync(0xffffffffu, acc1[e], off);
        }
    }

    // ---- Phase 2: lane-parallel softmax + gumbel top-2 ----
    // Lanes 0-7 handle (row r0, expert e=lane); lanes 8-15 handle (r1, e=lane-8).
    // Lanes 16-31 duplicate lanes 0-15 (harmless; keeps shuffles full-warp).
    {
        const int e    = lane & 7;
        const int half = (lane >> 3) & 1;
        const int row  = half ? r1 : r0;

        // static select acc[e] (no dynamic indexing -> no local spill)
        float v0 = acc0[0], v1 = acc1[0];
#pragma unroll
        for (int k = 1; k < EE; k++) {
            v0 = (e == k) ? acc0[k] : v0;
            v1 = (e == k) ? acc1[k] : v1;
        }
        float le = (half ? v1 : v0) + __ldg(bias + e);

        // group-of-8 max
        float m = le;
#pragma unroll
        for (int off = 4; off; off >>= 1)
            m = fmaxf(m, __shfl_xor_sync(0xffffffffu, m, off));
        float p = __expf(le - m);
        float s = p;
#pragma unroll
        for (int off = 4; off; off >>= 1)
            s += __shfl_xor_sync(0xffffffffu, s, off);
        float lp = logf(p / s + 1e-9f);       // one logf per lane, 8 in parallel

        float u = __ldg(noise + (size_t)row * EE + e) * (1.0f - 2e-7f) + 1e-7f;
        float y = lp - logf(-logf(u));

        // top-1 argmax over the 8-lane group (ties -> lowest index)
        float by = y; int bi = e;
#pragma unroll
        for (int off = 4; off; off >>= 1) {
            float oy = __shfl_xor_sync(0xffffffffu, by, off);
            int   oi = __shfl_xor_sync(0xffffffffu, bi, off);
            if (oy > by || (oy == by && oi < bi)) { by = oy; bi = oi; }
        }
        const int i0 = bi;
        // top-2: mask out i0, reduce again
        float y2 = (e == i0) ? -1e30f : y;
        float by2 = y2; int bi2 = e;
#pragma unroll
        for (int off = 4; off; off >>= 1) {
            float oy = __shfl_xor_sync(0xffffffffu, by2, off);
            int   oi = __shfl_xor_sync(0xffffffffu, bi2, off);
            if (oy > by2 || (oy == by2 && oi < bi2)) { by2 = oy; bi2 = oi; }
        }
        const int i1 = bi2;

        // fetch lp[i0], lp[i1] from within this 8-lane group
        float lp0 = __shfl_sync(0xffffffffu, lp, (lane & 24) | i0);
        float lp1 = __shfl_sync(0xffffffffu, lp, (lane & 24) | i1);

        if ((lane & 7) == 0 && lane < 16) {
            g_idx[row] = make_int2(i0, i1);
            float adv = __ldg(rewards + row) - __ldg(baseline);
            s_aux[warp * 2 + half] = adv * (lp0 + lp1);
        }
    }

    // ---- Aux partial + last-CTA finale (deterministic reduction order) ----
    __syncthreads();
    if (warp == 0) {
        int is_last = 0;
        if (lane == 0) {
            float s = 0.0f;
#pragma unroll
            for (int i = 0; i < ROWS_PER_CTA; i++) s += s_aux[i];
            g_aux_part[blockIdx.x] = s;
            __threadfence();
            unsigned p = atomicAdd(&g_ctr, 1u);
            is_last = (p == NCTA - 1);
        }
        is_last = __shfl_sync(0xffffffffu, is_last, 0);
        if (is_last) {
            double s = 0.0;
#pragma unroll
            for (int k = 0; k < NCTA / 32; k++)
                s += (double)__ldcg(&g_aux_part[lane + 32 * k]);
#pragma unroll
            for (int off = 16; off > 0; off >>= 1)
                s += __shfl_xor_sync(0xffffffffu, s, off);
            if (lane == 0) {
                out[out_size - 1] = -(float)(s / (double)BT);
                g_ctr = 0;                    // reset for next graph replay
            }
        }
    }
}

// ========================== Kernel B: combine ============================
// Streaming gather-average; 2 rows batched per step -> 4 LDG.128 in flight.
__global__ __launch_bounds__(TPB) void rlgate_combine_kernel(
    const float* __restrict__ eo,         // [E, BT, D]
    float* __restrict__ out)              // [BT, D]
{
    __shared__ int2 s_idx[CROWS];

    const int tid  = threadIdx.x;
    const int base = blockIdx.x * CROWS;

    if (tid < CROWS) s_idx[tid] = g_idx[base + tid];
    __syncthreads();

#pragma unroll
    for (int rp = 0; rp < CROWS; rp += 2) {
        const int row0 = base + rp;
        const int row1 = base + rp + 1;
        const int2 iA = s_idx[rp];
        const int2 iB = s_idx[rp + 1];

        const float4* pa = (const float4*)(eo + ((size_t)iA.x * BT + row0) * DD);
        const float4* pb = (const float4*)(eo + ((size_t)iA.y * BT + row0) * DD);
        const float4* pc = (const float4*)(eo + ((size_t)iB.x * BT + row1) * DD);
        const float4* pd = (const float4*)(eo + ((size_t)iB.y * BT + row1) * DD);

        float4 va = __ldcs(pa + tid);
        float4 vb = __ldcs(pb + tid);
        float4 vc = __ldcs(pc + tid);
        float4 vd = __ldcs(pd + tid);

        float4 r0v, r1v;
        r0v.x = (va.x + vb.x) * 0.5f;
        r0v.y = (va.y + vb.y) * 0.5f;
        r0v.z = (va.z + vb.z) * 0.5f;
        r0v.w = (va.w + vb.w) * 0.5f;
        r1v.x = (vc.x + vd.x) * 0.5f;
        r1v.y = (vc.y + vd.y) * 0.5f;
        r1v.z = (vc.z + vd.z) * 0.5f;
        r1v.w = (vc.w + vd.w) * 0.5f;

        __stcs((float4*)(out + (size_t)row0 * DD) + tid, r0v);
        __stcs((float4*)(out + (size_t)row1 * DD) + tid, r1v);
    }
}

extern "C" void kernel_launch(void* const* d_in, const int* in_sizes, int n_in,
                              void* d_out, int out_size) {
    const float* x        = (const float*)d_in[0];
    const float* eo       = (const float*)d_in[1];
    const float* rewards  = (const float*)d_in[2];
    const float* W        = (const float*)d_in[3];
    const float* bias     = (const float*)d_in[4];
    const float* baseline = (const float*)d_in[5];
    const float* noise    = (const float*)d_in[6];
    // d_in[7] = top_k (K=2 hardcoded to match problem shapes)
    float* out = (float*)d_out;

    rlgate_gate_kernel<<<NCTA, TPB>>>(x, rewards, W, bias, baseline, noise,
                                      out, out_size);
    rlgate_combine_kernel<<<NCCTA, TPB>>>(eo, out);
}

// round 8
// speedup vs baseline: 1.4469x; 1.4469x over previous
#include <cuda_runtime.h>
#include <math.h>

// Problem constants (B=4, T=2048, D=1024, E=8, K=2)
#define BT           8192
#define DD           1024
#define EE           8
#define TPB          256
#define ROWS_PER_CTA 16
#define NCTA         (BT / ROWS_PER_CTA)   // 512

__device__ float        g_aux_part[NCTA];
__device__ unsigned int g_ctr;             // zero-init; self-resets each launch

__global__ __launch_bounds__(TPB, 4) void rlgate_main_kernel(
    const float* __restrict__ x,          // [BT, D]
    const float* __restrict__ eo,         // [E, BT, D]
    const float* __restrict__ rewards,    // [BT]
    const float* __restrict__ W,          // [D, E]
    const float* __restrict__ bias,       // [E]
    const float* __restrict__ baseline,   // scalar
    const float* __restrict__ noise,      // [BT, E]
    float* __restrict__ out,              // [BT*D (+aux slot)]
    int out_size)
{
    __shared__ float Wt[EE][DD];          // transposed gate weights, 32KB
    __shared__ float s_aux[ROWS_PER_CTA];

    const int tid  = threadIdx.x;
    const int lane = tid & 31;
    const int warp = tid >> 5;

    const int r0 = blockIdx.x * ROWS_PER_CTA + warp * 2;
    const int r1 = r0 + 1;

    const float4* x0 = (const float4*)(x + (size_t)r0 * DD);
    const float4* x1 = (const float4*)(x + (size_t)r1 * DD);

    // Depth-4 prefetch: iterations 0..3 issued BEFORE the smem barrier.
    float4 pa[4], pb[4];
#pragma unroll
    for (int k = 0; k < 4; k++) {
        pa[k] = __ldg(x0 + lane + 32 * k);
        pb[k] = __ldg(x1 + lane + 32 * k);
    }

    // ---- Load W [D,E] -> smem transposed Wt[E][D] (vectorized) ----
    {
        const float4* W4 = (const float4*)W;
#pragma unroll
        for (int k = 0; k < (DD * EE / 4) / TPB; k++) {
            int i = tid + k * TPB;
            float4 v = __ldg(W4 + i);
            int d  = i >> 1;
            int e0 = (i & 1) * 4;
            Wt[e0 + 0][d] = v.x;
            Wt[e0 + 1][d] = v.y;
            Wt[e0 + 2][d] = v.z;
            Wt[e0 + 3][d] = v.w;
        }
    }
    __syncthreads();

    // ---- Phase 1: logits for both rows (depth-4 pipelined) ----
    float acc0[EE], acc1[EE];
#pragma unroll
    for (int e = 0; e < EE; e++) { acc0[e] = 0.0f; acc1[e] = 0.0f; }

    const float4* Wt4 = (const float4*)Wt;   // Wt4[e*256 + j]

#pragma unroll
    for (int i = 0; i < 8; i++) {
        float4 a4 = pa[i & 3];
        float4 b4 = pb[i & 3];
        if (i < 4) {                          // refill slot with iter i+4
            int jn = lane + 32 * (i + 4);
            pa[i & 3] = __ldg(x0 + jn);
            pb[i & 3] = __ldg(x1 + jn);
        }
        int j = lane + 32 * i;
#pragma unroll
        for (int e = 0; e < EE; e++) {
            float4 w = Wt4[e * (DD / 4) + j];
            acc0[e] = fmaf(a4.x, w.x, fmaf(a4.y, w.y, fmaf(a4.z, w.z, fmaf(a4.w, w.w, acc0[e]))));
            acc1[e] = fmaf(b4.x, w.x, fmaf(b4.y, w.y, fmaf(b4.z, w.z, fmaf(b4.w, w.w, acc1[e]))));
        }
    }

    // ---- Hierarchical reduce: 16 values over 32 lanes in 31 SHFLs.
    // Ends with lane L holding the logit for row = bit3(L), e = L & 7.
    float le;
    {
        // Round A (xor 16): all 16 values, halves become identical.
#pragma unroll
        for (int j = 0; j < EE; j++) {
            acc0[j] += __shfl_xor_sync(0xffffffffu, acc0[j], 16);
            acc1[j] += __shfl_xor_sync(0xffffffffu, acc1[j], 16);
        }
        // Round B (xor 8): keep row selected by lane bit 3.
        const bool rsel = (lane & 8) != 0;
        float t[8];
#pragma unroll
        for (int j = 0; j < EE; j++) {
            float send = rsel ? acc0[j] : acc1[j];
            float recv = __shfl_xor_sync(0xffffffffu, send, 8);
            t[j] = (rsel ? acc1[j] : acc0[j]) + recv;
        }
        // Round C (xor 4): keep e-half selected by lane bit 2.
        const bool hi = (lane & 4) != 0;
        float u4[4];
#pragma unroll
        for (int k = 0; k < 4; k++) {
            float send = hi ? t[k] : t[k + 4];
            float recv = __shfl_xor_sync(0xffffffffu, send, 4);
            u4[k] = (hi ? t[k + 4] : t[k]) + recv;
        }
        // Round D (xor 2): lane bit 1.
        const bool b1 = (lane & 2) != 0;
        float w2[2];
#pragma unroll
        for (int k = 0; k < 2; k++) {
            float send = b1 ? u4[k] : u4[k + 2];
            float recv = __shfl_xor_sync(0xffffffffu, send, 2);
            w2[k] = (b1 ? u4[k + 2] : u4[k]) + recv;
        }
        // Round E (xor 1): lane bit 0.
        const bool b0 = (lane & 1) != 0;
        {
            float send = b0 ? w2[0] : w2[1];
            float recv = __shfl_xor_sync(0xffffffffu, send, 1);
            le = (b0 ? w2[1] : w2[0]) + recv;
        }
    }

    // ---- Phase 2: lane-parallel softmax + gumbel top-2 ----
    // lane = row*8 + e for lanes 0..15; lanes 16..31 duplicate.
    const int e    = lane & 7;
    const int half = (lane >> 3) & 1;
    const int row  = half ? r1 : r0;
    int i0, i1;
    float lp0, lp1;
    {
        le += __ldg(bias + e);

        float m = le;
#pragma unroll
        for (int off = 4; off; off >>= 1)
            m = fmaxf(m, __shfl_xor_sync(0xffffffffu, m, off));
        float p = __expf(le - m);
        float s = p;
#pragma unroll
        for (int off = 4; off; off >>= 1)
            s += __shfl_xor_sync(0xffffffffu, s, off);
        float lp = __logf(p / s + 1e-9f);     // absolute-error safe

        float u = __ldg(noise + (size_t)row * EE + e) * (1.0f - 2e-7f) + 1e-7f;
        // inner log needs full precision near u ~= 1; outer is abs-error safe
        float y = lp - __logf(-logf(u));

        float by = y; int bi = e;
#pragma unroll
        for (int off = 4; off; off >>= 1) {
            float oy = __shfl_xor_sync(0xffffffffu, by, off);
            int   oi = __shfl_xor_sync(0xffffffffu, bi, off);
            if (oy > by || (oy == by && oi < bi)) { by = oy; bi = oi; }
        }
        i0 = bi;
        float y2 = (e == i0) ? -1e30f : y;
        float by2 = y2; int bi2 = e;
#pragma unroll
        for (int off = 4; off; off >>= 1) {
            float oy = __shfl_xor_sync(0xffffffffu, by2, off);
            int   oi = __shfl_xor_sync(0xffffffffu, bi2, off);
            if (oy > by2 || (oy == by2 && oi < bi2)) { by2 = oy; bi2 = oi; }
        }
        i1 = bi2;

        lp0 = __shfl_sync(0xffffffffu, lp, (lane & 24) | i0);
        lp1 = __shfl_sync(0xffffffffu, lp, (lane & 24) | i1);

        if ((lane & 15) == 0 || lane == 8) {  // lanes 0 and 8 (and 16/24 no-op dup guard)
            if (lane < 16) {
                float adv = __ldg(rewards + row) - __ldg(baseline);
                s_aux[warp * 2 + half] = adv * (lp0 + lp1);
            }
        }
    }
    // Broadcast expert pairs: lane0 -> r0, lane8 -> r1.
    const int a0 = __shfl_sync(0xffffffffu, i0, 0);
    const int a1 = __shfl_sync(0xffffffffu, i1, 0);
    const int b0 = __shfl_sync(0xffffffffu, i0, 8);
    const int b1 = __shfl_sync(0xffffffffu, i1, 8);

    // ---- Phase 3: combine gather (top-2 average), no barrier before it ----
    {
        const float4* qa = (const float4*)(eo + ((size_t)a0 * BT + r0) * DD);
        const float4* qb = (const float4*)(eo + ((size_t)a1 * BT + r0) * DD);
        const float4* qc = (const float4*)(eo + ((size_t)b0 * BT + r1) * DD);
        const float4* qd = (const float4*)(eo + ((size_t)b1 * BT + r1) * DD);
        float4* o0 = (float4*)(out + (size_t)r0 * DD);
        float4* o1 = (float4*)(out + (size_t)r1 * DD);
#pragma unroll
        for (int i = 0; i < 8; i++) {
            int j = lane + 32 * i;
            float4 va = __ldcs(qa + j);
            float4 vb = __ldcs(qb + j);
            float4 vc = __ldcs(qc + j);
            float4 vd = __ldcs(qd + j);
            float4 r0v, r1v;
            r0v.x = (va.x + vb.x) * 0.5f;
            r0v.y = (va.y + vb.y) * 0.5f;
            r0v.z = (va.z + vb.z) * 0.5f;
            r0v.w = (va.w + vb.w) * 0.5f;
            r1v.x = (vc.x + vd.x) * 0.5f;
            r1v.y = (vc.y + vd.y) * 0.5f;
            r1v.z = (vc.z + vd.z) * 0.5f;
            r1v.w = (vc.w + vd.w) * 0.5f;
            __stcs(o0 + j, r0v);
            __stcs(o1 + j, r1v);
        }
    }

    // ---- Aux finale at the very end (single barrier) ----
    __syncthreads();
    if (warp == 0) {
        int is_last = 0;
        if (lane == 0) {
            float s = 0.0f;
#pragma unroll
            for (int i = 0; i < ROWS_PER_CTA; i++) s += s_aux[i];
            g_aux_part[blockIdx.x] = s;
            __threadfence();
            unsigned p = atomicAdd(&g_ctr, 1u);
            is_last = (p == NCTA - 1);
        }
        is_last = __shfl_sync(0xffffffffu, is_last, 0);
        if (is_last) {
            double s = 0.0;
#pragma unroll
            for (int k = 0; k < NCTA / 32; k++)
                s += (double)__ldcg(&g_aux_part[lane + 32 * k]);
#pragma unroll
            for (int off = 16; off > 0; off >>= 1)
                s += __shfl_xor_sync(0xffffffffu, s, off);
            if (lane == 0) {
                out[out_size - 1] = -(float)(s / (double)BT);
                g_ctr = 0;                    // reset for next graph replay
            }
        }
    }
}

extern "C" void kernel_launch(void* const* d_in, const int* in_sizes, int n_in,
                              void* d_out, int out_size) {
    const float* x        = (const float*)d_in[0];
    const float* eo       = (const float*)d_in[1];
    const float* rewards  = (const float*)d_in[2];
    const float* W        = (const float*)d_in[3];
    const float* bias     = (const float*)d_in[4];
    const float* baseline = (const float*)d_in[5];
    const float* noise    = (const float*)d_in[6];
    // d_in[7] = top_k (K=2 hardcoded to match problem shapes)
    float* out = (float*)d_out;

    rlgate_main_kernel<<<NCTA, TPB>>>(x, eo, rewards, W, bias, baseline, noise,
                                      out, out_size);
}